// round 3
// baseline (speedup 1.0000x reference)
#include <cuda_runtime.h>
#include <cuda_bf16.h>

// Problem: B=4, T=4096, E=1024, H=64
//   Q = idx@Wq+bq ; K = idx@Wk+bk ; V = idx@Wv+bv
//   out = (Q K^T) * E^-0.5 @ V      (no softmax, no mask in reference!)
// Associativity: out = E^-0.5 * Q @ (K^T V), with K^T V only [64,64] per batch.
// Work: 6.44 GF projection GEMM (dominant) + 2 * 134 MF tiny GEMMs.
// This round: projection inner loop uses packed fma.rn.f32x2 (2x fp32 FMA rate).

#define B_  4
#define T_  4096
#define E_  1024
#define H_  64
#define BT_ (B_ * T_)          // 16384
#define SCALE_ 0.03125f        // 1024^-0.5

// ---------------- scratch (no allocations allowed) ----------------
__device__ float g_Q[BT_ * H_];          // 4 MB
__device__ float g_K[BT_ * H_];          // 4 MB
__device__ float g_V[BT_ * H_];          // 4 MB
__device__ float g_Mpart[B_ * 64 * H_ * H_];  // [b][chunk][h1][h2], 4 MB
__device__ float g_M[B_ * H_ * H_];      // 64 KB

// packed f32x2 helpers --------------------------------------------------------
__device__ __forceinline__ void fma_f32x2(unsigned long long& d,
                                          unsigned long long a,
                                          unsigned long long b) {
    asm("fma.rn.f32x2 %0, %1, %2, %0;" : "+l"(d) : "l"(a), "l"(b));
}
__device__ __forceinline__ void unpack_f32x2(float& lo, float& hi,
                                             unsigned long long v) {
    asm("mov.b64 {%0, %1}, %2;" : "=f"(lo), "=f"(hi) : "l"(v));
}

// ---------------------------------------------------------------------------
// Kernel A: fused QKV projection.  C[16384 x 64] = idx[16384 x 1024] @ W + b
// grid = (M/128, 3) ; blockIdx.y selects (Wq,bq,g_Q)/(Wk,..)/(Wv,..).
// Tile BM=128, BN=64, BK=16; 256 threads.
// Per thread: 4 m-row-PAIRS (packed f32x2) x 4 n  = 8x4 outputs.
//   As: k-major [16][132]  (transposed on store; LDS.64 row-pairs)
//   Bdup: [16][128], every B value duplicated {b,b} (splat via LDS.64)
// __launch_bounds__(256,3): 384 CTAs = ONE wave (148 SMs * 3 = 444 slots).
// ---------------------------------------------------------------------------
#define AS_S 132   // As row stride (floats); 132%32=4 -> transposed STS only 2-way

__global__ __launch_bounds__(256, 3)
void qkv_gemm(const float* __restrict__ idx,
              const float* __restrict__ Wq, const float* __restrict__ bq,
              const float* __restrict__ Wk, const float* __restrict__ bk,
              const float* __restrict__ Wv, const float* __restrict__ bv)
{
    __shared__ float As[16 * AS_S];     // [k][m], 8448 B
    __shared__ float Bdup[16 * 128];    // [k][2n] duplicated, 8192 B

    const int by = blockIdx.y;
    const float* __restrict__ W    = (by == 0) ? Wq : (by == 1) ? Wk : Wv;
    const float* __restrict__ bias = (by == 0) ? bq : (by == 1) ? bk : bv;
    float* __restrict__ out        = (by == 0) ? g_Q : (by == 1) ? g_K : g_V;

    const int tid = threadIdx.x;
    const int tx = tid & 15;        // n  = tx + 16*j
    const int ty = tid >> 4;        // m  = 2*ty + 32*ip (+1)
    const int m0 = blockIdx.x * 128;

    unsigned long long acc[4][4];
#pragma unroll
    for (int i = 0; i < 4; ++i)
#pragma unroll
        for (int j = 0; j < 4; ++j) acc[i][j] = 0ULL;

    for (int k0 = 0; k0 < E_; k0 += 16) {
        // ---- load A tile 128m x 16k, store TRANSPOSED into As[k][m] ----
#pragma unroll
        for (int q = 0; q < 2; ++q) {
            int l   = tid + q * 256;
            int row = l >> 2;            // m within tile
            int kq  = (l & 3) * 4;       // k within tile
            float4 v = *reinterpret_cast<const float4*>(
                idx + (size_t)(m0 + row) * E_ + k0 + kq);
            As[(kq + 0) * AS_S + row] = v.x;
            As[(kq + 1) * AS_S + row] = v.y;
            As[(kq + 2) * AS_S + row] = v.z;
            As[(kq + 3) * AS_S + row] = v.w;
        }
        // ---- load B tile 16k x 64n, store DUPLICATED into Bdup[k][2n] ----
        {
            int kk = tid >> 4;
            int n4 = (tid & 15) * 4;
            float4 v = *reinterpret_cast<const float4*>(
                W + (size_t)(k0 + kk) * H_ + n4);
            float2* bp = reinterpret_cast<float2*>(&Bdup[kk * 128 + 2 * n4]);
            bp[0] = make_float2(v.x, v.x);
            bp[1] = make_float2(v.y, v.y);
            bp[2] = make_float2(v.z, v.z);
            bp[3] = make_float2(v.w, v.w);
        }
        __syncthreads();

#pragma unroll
        for (int kk = 0; kk < 16; ++kk) {
            unsigned long long av[4], bv_[4];
#pragma unroll
            for (int i = 0; i < 4; ++i)
                av[i] = *reinterpret_cast<const unsigned long long*>(
                    &As[kk * AS_S + 2 * ty + 32 * i]);
#pragma unroll
            for (int j = 0; j < 4; ++j)
                bv_[j] = *reinterpret_cast<const unsigned long long*>(
                    &Bdup[kk * 128 + 2 * (tx + 16 * j)]);
#pragma unroll
            for (int i = 0; i < 4; ++i)
#pragma unroll
                for (int j = 0; j < 4; ++j)
                    fma_f32x2(acc[i][j], av[i], bv_[j]);
        }
        __syncthreads();
    }

#pragma unroll
    for (int j = 0; j < 4; ++j) {
        int n = tx + 16 * j;
        float bb = bias[n];
#pragma unroll
        for (int i = 0; i < 4; ++i) {
            float lo, hi;
            unpack_f32x2(lo, hi, acc[i][j]);
            int m = m0 + 2 * ty + 32 * i;
            out[(size_t)m * H_ + n]       = lo + bb;
            out[(size_t)(m + 1) * H_ + n] = hi + bb;
        }
    }
}

// ---------------------------------------------------------------------------
// Kernel B: partial M = K^T V per (batch, 64-row chunk of T).
// grid = (64 chunks, B), 256 threads, 4x4 outputs/thread.
// ---------------------------------------------------------------------------
__global__ __launch_bounds__(256, 2)
void ktv_kernel()
{
    __shared__ float Ks[64][68];
    __shared__ float Vs[64][68];

    const int cx = blockIdx.x;      // chunk
    const int b  = blockIdx.y;
    const int t0 = cx * 64;
    const int tid = threadIdx.x;
    const int tx = tid & 15;
    const int ty = tid >> 4;

    const float* __restrict__ Kp = g_K + ((size_t)b * T_ + t0) * H_;
    const float* __restrict__ Vp = g_V + ((size_t)b * T_ + t0) * H_;

#pragma unroll
    for (int q = 0; q < 4; ++q) {
        int l   = tid + q * 256;
        int row = l >> 4;
        int c4  = (l & 15) * 4;
        *reinterpret_cast<float4*>(&Ks[row][c4]) =
            *reinterpret_cast<const float4*>(Kp + (size_t)row * H_ + c4);
        *reinterpret_cast<float4*>(&Vs[row][c4]) =
            *reinterpret_cast<const float4*>(Vp + (size_t)row * H_ + c4);
    }
    __syncthreads();

    float acc[4][4];
#pragma unroll
    for (int i = 0; i < 4; ++i)
#pragma unroll
        for (int j = 0; j < 4; ++j) acc[i][j] = 0.f;

#pragma unroll 8
    for (int t = 0; t < 64; ++t) {
        float a[4], v[4];
#pragma unroll
        for (int i = 0; i < 4; ++i) a[i] = Ks[t][ty + 16 * i];
#pragma unroll
        for (int j = 0; j < 4; ++j) v[j] = Vs[t][tx + 16 * j];
#pragma unroll
        for (int i = 0; i < 4; ++i)
#pragma unroll
            for (int j = 0; j < 4; ++j)
                acc[i][j] = fmaf(a[i], v[j], acc[i][j]);
    }

    float* __restrict__ outp = g_Mpart + ((size_t)b * 64 + cx) * (H_ * H_);
#pragma unroll
    for (int i = 0; i < 4; ++i) {
        int h1 = ty + 16 * i;
#pragma unroll
        for (int j = 0; j < 4; ++j) {
            int h2 = tx + 16 * j;
            outp[h1 * H_ + h2] = acc[i][j];
        }
    }
}

// ---------------------------------------------------------------------------
// Kernel B2: reduce 64 chunk-partials -> g_M.  B*4096 outputs.
// ---------------------------------------------------------------------------
__global__ __launch_bounds__(256)
void reduce_kernel()
{
    int g = blockIdx.x * 256 + threadIdx.x;   // 0 .. B*4096-1
    int b = g >> 12;
    int e = g & 4095;
    const float* __restrict__ p = g_Mpart + (size_t)b * 64 * 4096 + e;
    float s = 0.f;
#pragma unroll 8
    for (int c = 0; c < 64; ++c) s += p[(size_t)c * 4096];
    g_M[(size_t)b * 4096 + e] = s;
}

// ---------------------------------------------------------------------------
// Kernel C: out = SCALE * Q @ M  per batch.  grid = (64 row-chunks, B).
// ---------------------------------------------------------------------------
__global__ __launch_bounds__(256, 2)
void qm_kernel(float* __restrict__ out)
{
    __shared__ float Qs[64][68];
    __shared__ float Ms[64][64];

    const int cx = blockIdx.x;
    const int b  = blockIdx.y;
    const int t0 = cx * 64;
    const int tid = threadIdx.x;
    const int tx = tid & 15;
    const int ty = tid >> 4;

    const float* __restrict__ Qp = g_Q + ((size_t)b * T_ + t0) * H_;
    const float* __restrict__ Mp = g_M + (size_t)b * 4096;

#pragma unroll
    for (int q = 0; q < 4; ++q) {
        int l   = tid + q * 256;
        int row = l >> 4;
        int c4  = (l & 15) * 4;
        *reinterpret_cast<float4*>(&Qs[row][c4]) =
            *reinterpret_cast<const float4*>(Qp + (size_t)row * H_ + c4);
        reinterpret_cast<float4*>(Ms)[l] =
            reinterpret_cast<const float4*>(Mp)[l];
    }
    __syncthreads();

    float acc[4][4];
#pragma unroll
    for (int i = 0; i < 4; ++i)
#pragma unroll
        for (int j = 0; j < 4; ++j) acc[i][j] = 0.f;

#pragma unroll 8
    for (int h = 0; h < 64; ++h) {
        float a[4], m[4];
#pragma unroll
        for (int i = 0; i < 4; ++i) a[i] = Qs[ty + 16 * i][h];
#pragma unroll
        for (int j = 0; j < 4; ++j) m[j] = Ms[h][tx + 16 * j];
#pragma unroll
        for (int i = 0; i < 4; ++i)
#pragma unroll
            for (int j = 0; j < 4; ++j)
                acc[i][j] = fmaf(a[i], m[j], acc[i][j]);
    }

    float* __restrict__ op = out + ((size_t)b * T_ + t0) * H_;
#pragma unroll
    for (int i = 0; i < 4; ++i) {
        int r = ty + 16 * i;
#pragma unroll
        for (int j = 0; j < 4; ++j) {
            int h = tx + 16 * j;
            op[(size_t)r * H_ + h] = SCALE_ * acc[i][j];
        }
    }
}

// ---------------------------------------------------------------------------
extern "C" void kernel_launch(void* const* d_in, const int* in_sizes, int n_in,
                              void* d_out, int out_size)
{
    const float* idx = (const float*)d_in[0];
    const float* Wq  = (const float*)d_in[1];
    const float* bq  = (const float*)d_in[2];
    const float* Wk  = (const float*)d_in[3];
    const float* bk  = (const float*)d_in[4];
    const float* Wv  = (const float*)d_in[5];
    const float* bv  = (const float*)d_in[6];
    float* out = (float*)d_out;

    qkv_gemm   <<<dim3(BT_ / 128, 3), 256>>>(idx, Wq, bq, Wk, bk, Wv, bv);
    ktv_kernel <<<dim3(64, B_), 256>>>();
    reduce_kernel<<<(B_ * 4096) / 256, 256>>>();
    qm_kernel  <<<dim3(64, B_), 256>>>(out);
}

// round 17
// speedup vs baseline: 1.4852x; 1.4852x over previous
#include <cuda_runtime.h>
#include <cuda_bf16.h>
#include <mma.h>
#include <cstdint>

using namespace nvcuda;

// Problem: B=4, T=4096, E=1024, H=64
//   out = E^-0.5 * Q @ (K^T V)   (reference has no mask/softmax)
// tcgen05 is NOT available (harness PTX targets plain sm_103, no 'a' features).
// Projection uses wmma bf16 HMMA (baseline PTX) with 2-term split precision:
//   x = hi + lo (bf16 each);  A@B ~= Ah@Bh + Ah@Bl + Al@Bh   (err ~2^-18)

#define B_  4
#define T_  4096
#define E_  1024
#define H_  64
#define BT_ (B_ * T_)          // 16384
#define SCALE_ 0.03125f        // 1024^-0.5

// ---------------- scratch (no allocations allowed) ----------------
__device__ float g_Q[BT_ * H_];
__device__ float g_K[BT_ * H_];
__device__ float g_V[BT_ * H_];
__device__ float g_Mpart[B_ * 64 * H_ * H_];
__device__ float g_M[B_ * H_ * H_];

// ---------------- projection tiling ----------------
#define BM 128
#define BN 64
#define BK 32
#define ASTR 40   // bf16 stride of A smem tiles (32 + 8 pad)
#define BSTR 72   // bf16 stride of B smem tiles (64 + 8 pad)
#define CSTR 68   // float stride of epilogue buffer (64 + 4 pad)
// load-phase bytes: 2*BM*ASTR*2 + 2*BK*BSTR*2 = 20480 + 9216 = 29696
// epilogue bytes:   BM*CSTR*4 = 34816  -> union size
#define SMEM_BYTES (BM * CSTR * 4)

// ---------------------------------------------------------------------------
// Kernel A: fused QKV projection on wmma bf16 tensor cores.
// grid = (BT/BM, 3); 256 threads = 8 warps in 2(m) x 4(n) layout.
// Each warp: 64m x 16n = 4 accumulator fragments.
// ---------------------------------------------------------------------------
__global__ __launch_bounds__(256)
void qkv_wmma(const float* __restrict__ idx,
              const float* __restrict__ Wq, const float* __restrict__ bq,
              const float* __restrict__ Wk, const float* __restrict__ bk,
              const float* __restrict__ Wv, const float* __restrict__ bv)
{
    __shared__ __align__(16) char smbuf[SMEM_BYTES];
    __nv_bfloat16* Ahi = reinterpret_cast<__nv_bfloat16*>(smbuf);
    __nv_bfloat16* Alo = Ahi + BM * ASTR;
    __nv_bfloat16* Bhi = Alo + BM * ASTR;
    __nv_bfloat16* Blo = Bhi + BK * BSTR;
    float* Cs = reinterpret_cast<float*>(smbuf);

    const int by = blockIdx.y;
    const float* __restrict__ W    = (by == 0) ? Wq : (by == 1) ? Wk : Wv;
    const float* __restrict__ bias = (by == 0) ? bq : (by == 1) ? bk : bv;
    float* __restrict__ out        = (by == 0) ? g_Q : (by == 1) ? g_K : g_V;

    const int tid = threadIdx.x;
    const int wid = tid >> 5;
    const int wm  = wid >> 2;      // 0..1
    const int wn  = wid & 3;       // 0..3
    const int m0  = blockIdx.x * BM;

    wmma::fragment<wmma::accumulator, 16, 16, 16, float> acc[4];
#pragma unroll
    for (int i = 0; i < 4; ++i) wmma::fill_fragment(acc[i], 0.0f);

    for (int k0 = 0; k0 < E_; k0 += BK) {
        // ---- A tile: 128m x 32k fp32 -> hi/lo bf16 ----
#pragma unroll
        for (int q = 0; q < 4; ++q) {
            int l   = q * 256 + tid;
            int row = l >> 3;
            int c4  = (l & 7) * 4;
            float4 v = *reinterpret_cast<const float4*>(
                idx + (size_t)(m0 + row) * E_ + k0 + c4);
            float vs[4] = {v.x, v.y, v.z, v.w};
            unsigned short hh[4], ll[4];
#pragma unroll
            for (int j = 0; j < 4; ++j) {
                __nv_bfloat16 h = __float2bfloat16(vs[j]);
                __nv_bfloat16 lo = __float2bfloat16(vs[j] - __bfloat162float(h));
                hh[j] = __bfloat16_as_ushort(h);
                ll[j] = __bfloat16_as_ushort(lo);
            }
            uint2 hp = make_uint2((uint32_t)hh[0] | ((uint32_t)hh[1] << 16),
                                  (uint32_t)hh[2] | ((uint32_t)hh[3] << 16));
            uint2 lp = make_uint2((uint32_t)ll[0] | ((uint32_t)ll[1] << 16),
                                  (uint32_t)ll[2] | ((uint32_t)ll[3] << 16));
            *reinterpret_cast<uint2*>(Ahi + row * ASTR + c4) = hp;
            *reinterpret_cast<uint2*>(Alo + row * ASTR + c4) = lp;
        }
        // ---- B tile: 32k x 64n fp32 -> hi/lo bf16 ----
#pragma unroll
        for (int q = 0; q < 2; ++q) {
            int l   = q * 256 + tid;
            int row = l >> 4;
            int c4  = (l & 15) * 4;
            float4 v = *reinterpret_cast<const float4*>(
                W + (size_t)(k0 + row) * H_ + c4);
            float vs[4] = {v.x, v.y, v.z, v.w};
            unsigned short hh[4], ll[4];
#pragma unroll
            for (int j = 0; j < 4; ++j) {
                __nv_bfloat16 h = __float2bfloat16(vs[j]);
                __nv_bfloat16 lo = __float2bfloat16(vs[j] - __bfloat162float(h));
                hh[j] = __bfloat16_as_ushort(h);
                ll[j] = __bfloat16_as_ushort(lo);
            }
            uint2 hp = make_uint2((uint32_t)hh[0] | ((uint32_t)hh[1] << 16),
                                  (uint32_t)hh[2] | ((uint32_t)hh[3] << 16));
            uint2 lp = make_uint2((uint32_t)ll[0] | ((uint32_t)ll[1] << 16),
                                  (uint32_t)ll[2] | ((uint32_t)ll[3] << 16));
            *reinterpret_cast<uint2*>(Bhi + row * BSTR + c4) = hp;
            *reinterpret_cast<uint2*>(Blo + row * BSTR + c4) = lp;
        }
        __syncthreads();

        // ---- compute: 2 k-steps of 16, 4 m-frags, 3 split terms ----
#pragma unroll
        for (int ks = 0; ks < BK; ks += 16) {
            wmma::fragment<wmma::matrix_b, 16, 16, 16, __nv_bfloat16,
                           wmma::row_major> bh, bl;
            wmma::load_matrix_sync(bh, Bhi + ks * BSTR + 16 * wn, BSTR);
            wmma::load_matrix_sync(bl, Blo + ks * BSTR + 16 * wn, BSTR);
#pragma unroll
            for (int i = 0; i < 4; ++i) {
                int ar = (64 * wm + 16 * i) * ASTR + ks;
                wmma::fragment<wmma::matrix_a, 16, 16, 16, __nv_bfloat16,
                               wmma::row_major> ah, al;
                wmma::load_matrix_sync(ah, Ahi + ar, ASTR);
                wmma::load_matrix_sync(al, Alo + ar, ASTR);
                wmma::mma_sync(acc[i], ah, bh, acc[i]);
                wmma::mma_sync(acc[i], ah, bl, acc[i]);
                wmma::mma_sync(acc[i], al, bh, acc[i]);
            }
        }
        __syncthreads();
    }

    // ---- epilogue: fragments -> smem (fp32), add bias, store ----
#pragma unroll
    for (int i = 0; i < 4; ++i)
        wmma::store_matrix_sync(Cs + (64 * wm + 16 * i) * CSTR + 16 * wn,
                                acc[i], CSTR, wmma::mem_row_major);
    __syncthreads();

#pragma unroll
    for (int q = 0; q < 8; ++q) {
        int l   = q * 256 + tid;
        int row = l >> 4;
        int c4  = (l & 15) * 4;
        float4 c  = *reinterpret_cast<const float4*>(Cs + row * CSTR + c4);
        float4 bb = *reinterpret_cast<const float4*>(bias + c4);
        float4 o;
        o.x = c.x + bb.x; o.y = c.y + bb.y;
        o.z = c.z + bb.z; o.w = c.w + bb.w;
        *reinterpret_cast<float4*>(out + (size_t)(m0 + row) * H_ + c4) = o;
    }
}

// ---------------------------------------------------------------------------
// Kernel B: partial M = K^T V per (batch, 64-row chunk of T).
// ---------------------------------------------------------------------------
__global__ __launch_bounds__(256, 2)
void ktv_kernel()
{
    __shared__ float Ks[64][68];
    __shared__ float Vs[64][68];

    const int cx = blockIdx.x;
    const int b  = blockIdx.y;
    const int t0 = cx * 64;
    const int tid = threadIdx.x;
    const int tx = tid & 15;
    const int ty = tid >> 4;

    const float* __restrict__ Kp = g_K + ((size_t)b * T_ + t0) * H_;
    const float* __restrict__ Vp = g_V + ((size_t)b * T_ + t0) * H_;

#pragma unroll
    for (int q = 0; q < 4; ++q) {
        int l   = tid + q * 256;
        int row = l >> 4;
        int c4  = (l & 15) * 4;
        *reinterpret_cast<float4*>(&Ks[row][c4]) =
            *reinterpret_cast<const float4*>(Kp + (size_t)row * H_ + c4);
        *reinterpret_cast<float4*>(&Vs[row][c4]) =
            *reinterpret_cast<const float4*>(Vp + (size_t)row * H_ + c4);
    }
    __syncthreads();

    float acc[4][4];
#pragma unroll
    for (int i = 0; i < 4; ++i)
#pragma unroll
        for (int j = 0; j < 4; ++j) acc[i][j] = 0.f;

#pragma unroll 8
    for (int t = 0; t < 64; ++t) {
        float a[4], v[4];
#pragma unroll
        for (int i = 0; i < 4; ++i) a[i] = Ks[t][ty + 16 * i];
#pragma unroll
        for (int j = 0; j < 4; ++j) v[j] = Vs[t][tx + 16 * j];
#pragma unroll
        for (int i = 0; i < 4; ++i)
#pragma unroll
            for (int j = 0; j < 4; ++j)
                acc[i][j] = fmaf(a[i], v[j], acc[i][j]);
    }

    float* __restrict__ outp = g_Mpart + ((size_t)b * 64 + cx) * (H_ * H_);
#pragma unroll
    for (int i = 0; i < 4; ++i) {
        int h1 = ty + 16 * i;
#pragma unroll
        for (int j = 0; j < 4; ++j)
            outp[h1 * H_ + tx + 16 * j] = acc[i][j];
    }
}

// ---------------------------------------------------------------------------
// Kernel B2: reduce 64 chunk-partials -> g_M.
// ---------------------------------------------------------------------------
__global__ __launch_bounds__(256)
void reduce_kernel()
{
    int g = blockIdx.x * 256 + threadIdx.x;
    int b = g >> 12;
    int e = g & 4095;
    const float* __restrict__ p = g_Mpart + (size_t)b * 64 * 4096 + e;
    float s = 0.f;
#pragma unroll 8
    for (int c = 0; c < 64; ++c) s += p[(size_t)c * 4096];
    g_M[(size_t)b * 4096 + e] = s;
}

// ---------------------------------------------------------------------------
// Kernel C: out = SCALE * Q @ M per batch.
// ---------------------------------------------------------------------------
__global__ __launch_bounds__(256, 2)
void qm_kernel(float* __restrict__ out)
{
    __shared__ float Qs[64][68];
    __shared__ float Ms[64][64];

    const int cx = blockIdx.x;
    const int b  = blockIdx.y;
    const int t0 = cx * 64;
    const int tid = threadIdx.x;
    const int tx = tid & 15;
    const int ty = tid >> 4;

    const float* __restrict__ Qp = g_Q + ((size_t)b * T_ + t0) * H_;
    const float* __restrict__ Mp = g_M + (size_t)b * 4096;

#pragma unroll
    for (int q = 0; q < 4; ++q) {
        int l   = tid + q * 256;
        int row = l >> 4;
        int c4  = (l & 15) * 4;
        *reinterpret_cast<float4*>(&Qs[row][c4]) =
            *reinterpret_cast<const float4*>(Qp + (size_t)row * H_ + c4);
        reinterpret_cast<float4*>(Ms)[l] =
            reinterpret_cast<const float4*>(Mp)[l];
    }
    __syncthreads();

    float acc[4][4];
#pragma unroll
    for (int i = 0; i < 4; ++i)
#pragma unroll
        for (int j = 0; j < 4; ++j) acc[i][j] = 0.f;

#pragma unroll 8
    for (int h = 0; h < 64; ++h) {
        float a[4], m[4];
#pragma unroll
        for (int i = 0; i < 4; ++i) a[i] = Qs[ty + 16 * i][h];
#pragma unroll
        for (int j = 0; j < 4; ++j) m[j] = Ms[h][tx + 16 * j];
#pragma unroll
        for (int i = 0; i < 4; ++i)
#pragma unroll
            for (int j = 0; j < 4; ++j)
                acc[i][j] = fmaf(a[i], m[j], acc[i][j]);
    }

    float* __restrict__ op = out + ((size_t)b * T_ + t0) * H_;
#pragma unroll
    for (int i = 0; i < 4; ++i) {
        int r = ty + 16 * i;
#pragma unroll
        for (int j = 0; j < 4; ++j)
            op[(size_t)r * H_ + tx + 16 * j] = SCALE_ * acc[i][j];
    }
}

// ---------------------------------------------------------------------------
extern "C" void kernel_launch(void* const* d_in, const int* in_sizes, int n_in,
                              void* d_out, int out_size)
{
    const float* idx = (const float*)d_in[0];
    const float* Wq  = (const float*)d_in[1];
    const float* bq  = (const float*)d_in[2];
    const float* Wk  = (const float*)d_in[3];
    const float* bk  = (const float*)d_in[4];
    const float* Wv  = (const float*)d_in[5];
    const float* bv  = (const float*)d_in[6];
    float* out = (float*)d_out;

    qkv_wmma   <<<dim3(BT_ / BM, 3), 256>>>(idx, Wq, bq, Wk, bk, Wv, bv);
    ktv_kernel <<<dim3(64, B_), 256>>>();
    reduce_kernel<<<(B_ * 4096) / 256, 256>>>();
    qm_kernel  <<<dim3(64, B_), 256>>>(out);
}